// round 3
// baseline (speedup 1.0000x reference)
#include <cuda_runtime.h>
#include <cuda_bf16.h>

#define NN 50000
#define EE 800000
#define TID ((int)threadIdx.x)

// Scratch: P = h@Wm1[0:128], Q = h@Wm1[128:256], agg = scatter-add of messages
__device__ float g_P[NN * 128];
__device__ float g_Q[NN * 128];
__device__ float g_agg[NN * 128];
// Normalized edge indices (int32) + detected input dtype mode
__device__ int g_src[EE];
__device__ int g_dst[EE];
__device__ int g_mode;   // 1 = input is int64, 0 = input is int32

__device__ __forceinline__ void red_add_v4(float* addr, float4 v) {
    asm volatile("red.global.add.v4.f32 [%0], {%1, %2, %3, %4};"
                 :: "l"(addr), "f"(v.x), "f"(v.y), "f"(v.z), "f"(v.w) : "memory");
}

// ---------------------------------------------------------------------------
// Kernel A: detect edge_index dtype. Reading int32 data as int64 yields
// idx[2i] + idx[2i+1]*2^32, which is only in [0,NN) if the next index is 0 —
// vanishingly unlikely for all 64 probes. Deterministic given the data.
// ---------------------------------------------------------------------------
__global__ void detect_idx_kernel(const void* __restrict__ eidx) {
    if (TID == 0) {
        const long long* p = (const long long*)eidx;
        int ok = 1;
        for (int i = 0; i < 64; ++i) {
            long long v = p[i];
            if (v < 0 || v >= NN) { ok = 0; break; }
        }
        g_mode = ok;
    }
}

// ---------------------------------------------------------------------------
// Kernel B: normalize edge indices to int32 scratch (also zeroes agg tail-free)
// ---------------------------------------------------------------------------
__global__ void convert_idx_kernel(const void* __restrict__ eidx) {
    int i = blockIdx.x * 256 + TID;
    if (i >= EE) return;
    if (g_mode) {
        const long long* p = (const long long*)eidx;
        g_src[i] = (int)p[i];
        g_dst[i] = (int)p[EE + i];
    } else {
        const int* p = (const int*)eidx;
        g_src[i] = p[i];
        g_dst[i] = p[EE + i];
    }
}

// ---------------------------------------------------------------------------
// Shared GEMM microkernel: C(64x128) += A(64xK, smem, row stride AST) @ B(Kx128, global)
// 256 threads, per-thread 4x8 microtile. acc must be pre-initialized.
// Bs is a 16x128 smem staging buffer. Caller must have synced before entry.
// ---------------------------------------------------------------------------
template<int K, int AST, bool RELU>
__device__ __forceinline__ void gemm_64xK_128(
    const float* __restrict__ As, const float* __restrict__ gB,
    float* Bs, float acc[4][8], int m0, int n0)
{
#pragma unroll 1
    for (int kc = 0; kc < K; kc += 16) {
        // stage 16x128 chunk of B: 512 float4, 2 per thread, coalesced
        const float4* src = reinterpret_cast<const float4*>(gB + kc * 128) + TID * 2;
        float4* dstp = reinterpret_cast<float4*>(Bs) + TID * 2;
        dstp[0] = src[0];
        dstp[1] = src[1];
        __syncthreads();
#pragma unroll
        for (int k = 0; k < 16; ++k) {
            float a[4];
#pragma unroll
            for (int i = 0; i < 4; ++i) a[i] = As[(m0 + i) * AST + kc + k];
            float4 b0 = *reinterpret_cast<const float4*>(Bs + k * 128 + n0);
            float4 b1 = *reinterpret_cast<const float4*>(Bs + k * 128 + n0 + 4);
            float b[8] = {b0.x, b0.y, b0.z, b0.w, b1.x, b1.y, b1.z, b1.w};
#pragma unroll
            for (int i = 0; i < 4; ++i)
#pragma unroll
                for (int j = 0; j < 8; ++j)
                    acc[i][j] = fmaf(a[i], b[j], acc[i][j]);
        }
        __syncthreads();
    }
    if (RELU) {
#pragma unroll
        for (int i = 0; i < 4; ++i)
#pragma unroll
            for (int j = 0; j < 8; ++j)
                acc[i][j] = fmaxf(acc[i][j], 0.0f);
    }
}

// ---------------------------------------------------------------------------
// Kernel 0: zero the aggregation buffer
// ---------------------------------------------------------------------------
__global__ void zero_agg_kernel() {
    int i = blockIdx.x * 256 + TID;
    if (i < NN * 32)
        reinterpret_cast<float4*>(g_agg)[i] = make_float4(0.f, 0.f, 0.f, 0.f);
}

// ---------------------------------------------------------------------------
// Kernel 1: P = h @ Wm1[0:128,:],  Q = h @ Wm1[128:256,:]   (no bias)
// ---------------------------------------------------------------------------
#define PQ_SMEM (64 * 132 * 4 + 16 * 128 * 4)
__global__ void __launch_bounds__(256)
pq_kernel(const float* __restrict__ h, const float* __restrict__ Wm1) {
    extern __shared__ float sm[];
    float* As = sm;                 // 64 x 132
    float* Bs = sm + 64 * 132;      // 16 x 128
    int base = blockIdx.x * 64;

    for (int s = TID; s < 64 * 32; s += 256) {
        int m = s >> 5, c4 = s & 31;
        int node = base + m;
        float4 v = make_float4(0.f, 0.f, 0.f, 0.f);
        if (node < NN) v = reinterpret_cast<const float4*>(h)[(size_t)node * 32 + c4];
        *reinterpret_cast<float4*>(As + m * 132 + c4 * 4) = v;
    }
    __syncthreads();

    int m0 = (TID / 16) * 4, n0 = (TID % 16) * 8;
    float acc[4][8];

    // P
#pragma unroll
    for (int i = 0; i < 4; ++i)
#pragma unroll
        for (int j = 0; j < 8; ++j) acc[i][j] = 0.f;
    gemm_64xK_128<128, 132, false>(As, Wm1, Bs, acc, m0, n0);
#pragma unroll
    for (int i = 0; i < 4; ++i) {
        int node = base + m0 + i;
        if (node < NN) {
            float* p = g_P + (size_t)node * 128 + n0;
            *reinterpret_cast<float4*>(p) = make_float4(acc[i][0], acc[i][1], acc[i][2], acc[i][3]);
            *reinterpret_cast<float4*>(p + 4) = make_float4(acc[i][4], acc[i][5], acc[i][6], acc[i][7]);
        }
    }

    // Q
#pragma unroll
    for (int i = 0; i < 4; ++i)
#pragma unroll
        for (int j = 0; j < 8; ++j) acc[i][j] = 0.f;
    gemm_64xK_128<128, 132, false>(As, Wm1 + 128 * 128, Bs, acc, m0, n0);
#pragma unroll
    for (int i = 0; i < 4; ++i) {
        int node = base + m0 + i;
        if (node < NN) {
            float* p = g_Q + (size_t)node * 128 + n0;
            *reinterpret_cast<float4*>(p) = make_float4(acc[i][0], acc[i][1], acc[i][2], acc[i][3]);
            *reinterpret_cast<float4*>(p + 4) = make_float4(acc[i][4], acc[i][5], acc[i][6], acc[i][7]);
        }
    }
}

// ---------------------------------------------------------------------------
// Kernel 2: per-edge messages + scatter-add
//   x  = relu(P[src] + Q[dst] + edge_attr @ Wm1[256:288,:] + bm1)
//   m  = relu(x @ Wm2 + bm2)
//   agg[dst] += m   (red.global.add.v4.f32)
// E = 800000 = 12500 tiles of exactly 64 edges — no guards needed.
// ---------------------------------------------------------------------------
#define EDGE_SMEM (64 * 132 * 4 + 64 * 132 * 4 + 64 * 36 * 4 + 16 * 128 * 4 + 64 * 8)
__global__ void __launch_bounds__(256)
edge_kernel(const float* __restrict__ edge_attr,
            const float* __restrict__ Wm1, const float* __restrict__ bm1,
            const float* __restrict__ Wm2, const float* __restrict__ bm2) {
    extern __shared__ float sm[];
    float* As = sm;                        // 64 x 132  (x_pre, then init for GEMM0)
    float* Xs = As + 64 * 132;             // 64 x 132
    float* Es = Xs + 64 * 132;             // 64 x 36
    float* Bs = Es + 64 * 36;              // 16 x 128 staging
    int* ssrc = reinterpret_cast<int*>(Bs + 16 * 128);  // 64
    int* sdst = ssrc + 64;                               // 64

    int base = blockIdx.x * 64;

    if (TID < 64) {
        ssrc[TID] = g_src[base + TID];
        sdst[TID] = g_dst[base + TID];
    }
    // edge_attr tile: 64 x 32 floats = 512 float4
    for (int s = TID; s < 64 * 8; s += 256) {
        int m = s >> 3, c4 = s & 7;
        *reinterpret_cast<float4*>(Es + m * 36 + c4 * 4) =
            reinterpret_cast<const float4*>(edge_attr)[(size_t)(base + m) * 8 + c4];
    }
    __syncthreads();

    // gather: As[e][:] = P[src[e]] + Q[dst[e]] + bm1
    for (int s = TID; s < 64 * 32; s += 256) {
        int m = s >> 5, c4 = s & 31;
        int sn = ssrc[m], dn = sdst[m];
        float4 p = reinterpret_cast<const float4*>(g_P)[(size_t)sn * 32 + c4];
        float4 q = reinterpret_cast<const float4*>(g_Q)[(size_t)dn * 32 + c4];
        float4 b = reinterpret_cast<const float4*>(bm1)[c4];
        *reinterpret_cast<float4*>(As + m * 132 + c4 * 4) =
            make_float4(p.x + q.x + b.x, p.y + q.y + b.y, p.z + q.z + b.z, p.w + q.w + b.w);
    }
    __syncthreads();

    int m0 = (TID / 16) * 4, n0 = (TID % 16) * 8;
    float acc[4][8];

    // GEMM0: X = relu(As + Es @ Wm1c)
#pragma unroll
    for (int i = 0; i < 4; ++i)
#pragma unroll
        for (int j = 0; j < 8; ++j) acc[i][j] = As[(m0 + i) * 132 + n0 + j];
    gemm_64xK_128<32, 36, true>(Es, Wm1 + 256 * 128, Bs, acc, m0, n0);
#pragma unroll
    for (int i = 0; i < 4; ++i) {
        float* p = Xs + (m0 + i) * 132 + n0;
        *reinterpret_cast<float4*>(p) = make_float4(acc[i][0], acc[i][1], acc[i][2], acc[i][3]);
        *reinterpret_cast<float4*>(p + 4) = make_float4(acc[i][4], acc[i][5], acc[i][6], acc[i][7]);
    }
    __syncthreads();

    // GEMM1: M = relu(X @ Wm2 + bm2)
#pragma unroll
    for (int i = 0; i < 4; ++i)
#pragma unroll
        for (int j = 0; j < 8; ++j) acc[i][j] = bm2[n0 + j];
    gemm_64xK_128<128, 132, true>(Xs, Wm2, Bs, acc, m0, n0);

    // scatter-add
#pragma unroll
    for (int i = 0; i < 4; ++i) {
        int d = sdst[m0 + i];
        float* p = g_agg + (size_t)d * 128 + n0;
        red_add_v4(p,     make_float4(acc[i][0], acc[i][1], acc[i][2], acc[i][3]));
        red_add_v4(p + 4, make_float4(acc[i][4], acc[i][5], acc[i][6], acc[i][7]));
    }
}

// ---------------------------------------------------------------------------
// Kernel 3: update
//   u = relu([h, agg] @ Wu1 + bu1);  out = h + u @ Wu2 + bu2
// ---------------------------------------------------------------------------
#define UPD_SMEM (64 * 260 * 4 + 64 * 132 * 4 + 16 * 128 * 4)
__global__ void __launch_bounds__(256)
update_kernel(const float* __restrict__ h,
              const float* __restrict__ Wu1, const float* __restrict__ bu1,
              const float* __restrict__ Wu2, const float* __restrict__ bu2,
              float* __restrict__ out) {
    extern __shared__ float sm[];
    float* As = sm;                 // 64 x 260  ([h | agg])
    float* Us = As + 64 * 260;      // 64 x 132
    float* Bs = Us + 64 * 132;      // 16 x 128
    int base = blockIdx.x * 64;

    for (int s = TID; s < 64 * 64; s += 256) {
        int m = s >> 6, c4 = s & 63;
        int node = base + m;
        float4 v = make_float4(0.f, 0.f, 0.f, 0.f);
        if (node < NN)
            v = (c4 < 32) ? reinterpret_cast<const float4*>(h)[(size_t)node * 32 + c4]
                          : reinterpret_cast<const float4*>(g_agg)[(size_t)node * 32 + (c4 - 32)];
        *reinterpret_cast<float4*>(As + m * 260 + c4 * 4) = v;
    }
    __syncthreads();

    int m0 = (TID / 16) * 4, n0 = (TID % 16) * 8;
    float acc[4][8];

    // U = relu([h,agg] @ Wu1 + bu1)
#pragma unroll
    for (int i = 0; i < 4; ++i)
#pragma unroll
        for (int j = 0; j < 8; ++j) acc[i][j] = bu1[n0 + j];
    gemm_64xK_128<256, 260, true>(As, Wu1, Bs, acc, m0, n0);
#pragma unroll
    for (int i = 0; i < 4; ++i) {
        float* p = Us + (m0 + i) * 132 + n0;
        *reinterpret_cast<float4*>(p) = make_float4(acc[i][0], acc[i][1], acc[i][2], acc[i][3]);
        *reinterpret_cast<float4*>(p + 4) = make_float4(acc[i][4], acc[i][5], acc[i][6], acc[i][7]);
    }
    __syncthreads();

    // out = h + U @ Wu2 + bu2
#pragma unroll
    for (int i = 0; i < 4; ++i)
#pragma unroll
        for (int j = 0; j < 8; ++j) acc[i][j] = bu2[n0 + j];
    gemm_64xK_128<128, 132, false>(Us, Wu2, Bs, acc, m0, n0);
#pragma unroll
    for (int i = 0; i < 4; ++i) {
        int node = base + m0 + i;
        if (node < NN) {
            float* p = out + (size_t)node * 128 + n0;
#pragma unroll
            for (int j = 0; j < 8; ++j)
                p[j] = As[(m0 + i) * 260 + n0 + j] + acc[i][j];
        }
    }
}

// ---------------------------------------------------------------------------
extern "C" void kernel_launch(void* const* d_in, const int* in_sizes, int n_in,
                              void* d_out, int out_size) {
    const float* h         = (const float*)d_in[0];
    const float* edge_attr = (const float*)d_in[1];
    const float* Wm1       = (const float*)d_in[2];
    const float* bm1       = (const float*)d_in[3];
    const float* Wm2       = (const float*)d_in[4];
    const float* bm2       = (const float*)d_in[5];
    const float* Wu1       = (const float*)d_in[6];
    const float* bu1       = (const float*)d_in[7];
    const float* Wu2       = (const float*)d_in[8];
    const float* bu2       = (const float*)d_in[9];
    const void*  eidx      = (const void*)d_in[10];
    float* out             = (float*)d_out;

    cudaFuncSetAttribute(pq_kernel,     cudaFuncAttributeMaxDynamicSharedMemorySize, PQ_SMEM);
    cudaFuncSetAttribute(edge_kernel,   cudaFuncAttributeMaxDynamicSharedMemorySize, EDGE_SMEM);
    cudaFuncSetAttribute(update_kernel, cudaFuncAttributeMaxDynamicSharedMemorySize, UPD_SMEM);

    detect_idx_kernel<<<1, 32>>>(eidx);
    convert_idx_kernel<<<(EE + 255) / 256, 256>>>(eidx);
    zero_agg_kernel<<<(NN * 32 + 255) / 256, 256>>>();
    pq_kernel<<<(NN + 63) / 64, 256, PQ_SMEM>>>(h, Wm1);
    edge_kernel<<<EE / 64, 256, EDGE_SMEM>>>(edge_attr, Wm1, bm1, Wm2, bm2);
    update_kernel<<<(NN + 63) / 64, 256, UPD_SMEM>>>(h, Wu1, bu1, Wu2, bu2, out);
}

// round 4
// speedup vs baseline: 1.0562x; 1.0562x over previous
#include <cuda_runtime.h>
#include <cuda_bf16.h>

#define NN 50000
#define EE 800000
#define TID ((int)threadIdx.x)
typedef unsigned long long u64;

// Scratch
__device__ float g_P[NN * 128];
__device__ float g_Q[NN * 128];
__device__ float g_agg[NN * 128];
__device__ int g_src[EE];
__device__ int g_dst[EE];
__device__ int g_mode;   // 1 = input is int64, 0 = int32

// ---------------- f32x2 helpers (FFMA2: 2 fp32 FMAs per instruction) ---------
__device__ __forceinline__ u64 pack_dup(float x) {
    u64 r; asm("mov.b64 %0, {%1, %1};" : "=l"(r) : "f"(x)); return r;
}
__device__ __forceinline__ u64 pack2(float x, float y) {
    u64 r; asm("mov.b64 %0, {%1, %2};" : "=l"(r) : "f"(x), "f"(y)); return r;
}
__device__ __forceinline__ float2 unpk(u64 v) {
    float2 f; asm("mov.b64 {%0, %1}, %2;" : "=f"(f.x), "=f"(f.y) : "l"(v)); return f;
}
__device__ __forceinline__ void ffma2(u64& d, u64 a, u64 b) {
    asm("fma.rn.f32x2 %0, %1, %2, %0;" : "+l"(d) : "l"(a), "l"(b));
}
__device__ __forceinline__ void red_add_v4(float* addr, float4 v) {
    asm volatile("red.global.add.v4.f32 [%0], {%1, %2, %3, %4};"
                 :: "l"(addr), "f"(v.x), "f"(v.y), "f"(v.z), "f"(v.w) : "memory");
}

// ---------------- index dtype detection / normalization ----------------------
__global__ void detect_idx_kernel(const void* __restrict__ eidx) {
    if (TID == 0) {
        const long long* p = (const long long*)eidx;
        int ok = 1;
        for (int i = 0; i < 64; ++i) {
            long long v = p[i];
            if (v < 0 || v >= NN) { ok = 0; break; }
        }
        g_mode = ok;
    }
}
__global__ void convert_idx_kernel(const void* __restrict__ eidx) {
    int i = blockIdx.x * 256 + TID;
    if (i >= EE) return;
    if (g_mode) {
        const long long* p = (const long long*)eidx;
        g_src[i] = (int)p[i];
        g_dst[i] = (int)p[EE + i];
    } else {
        const int* p = (const int*)eidx;
        g_src[i] = p[i];
        g_dst[i] = p[EE + i];
    }
}
__global__ void zero_agg_kernel() {
    int i = blockIdx.x * 256 + TID;
    if (i < NN * 32)
        reinterpret_cast<float4*>(g_agg)[i] = make_float4(0.f, 0.f, 0.f, 0.f);
}

// ---------------- weight staging: row-major Kx128 -> swizzled cells ----------
// dst cell layout: cell(k, c) at dst[(k<<5) + (c ^ (k&31))], cell = 16B (float4)
__device__ __forceinline__ void stage_W(float4* dst, const float4* __restrict__ src, int krows) {
    for (int s = TID; s < (krows << 5); s += 512) {
        int k = s >> 5, c = s & 31;
        dst[(k << 5) + (c ^ (k & 31))] = src[s];
    }
}

// ---------------- FFMA2 GEMM microkernel ------------------------------------
// C(128x128) += A(128xK smem row-major, stride AST) @ B(Kx128 smem, swizzled cells)
// 512 threads; thread tile 4 rows x 8 cols; acc2[i][jp] = packed col-pair.
template<int K, int AST>
__device__ __forceinline__ void mm(const float* __restrict__ As,
                                   const ulonglong2* __restrict__ Bu,
                                   u64 acc2[4][4], int m0, int cn) {
#pragma unroll 4
    for (int k = 0; k < K; ++k) {
        int sw = k & 31;
        int kb = k << 5;
        ulonglong2 p0 = Bu[kb + (cn ^ sw)];
        ulonglong2 p1 = Bu[kb + ((cn ^ sw) ^ 1)];
#pragma unroll
        for (int i = 0; i < 4; ++i) {
            u64 a = pack_dup(As[(m0 + i) * AST + k]);
            ffma2(acc2[i][0], a, p0.x);
            ffma2(acc2[i][1], a, p0.y);
            ffma2(acc2[i][2], a, p1.x);
            ffma2(acc2[i][3], a, p1.y);
        }
    }
}

// ---------------------------------------------------------------------------
// Kernel 1: P = h @ Wm1[0:128], Q = h @ Wm1[128:256]
// ---------------------------------------------------------------------------
#define PQ_SMEM (128 * 132 * 4 + 128 * 32 * 16)
__global__ void __launch_bounds__(512, 1)
pq_kernel(const float* __restrict__ h, const float* __restrict__ Wm1) {
    extern __shared__ float sm[];
    float* As = sm;                                   // 128 x 132
    float4* Ws = (float4*)(sm + 128 * 132);           // 128 k-rows x 32 cells
    const ulonglong2* Wu = (const ulonglong2*)Ws;
    int base = blockIdx.x * 128;

    for (int s = TID; s < 128 * 32; s += 512) {
        int m = s >> 5, c4 = s & 31;
        int node = base + m;
        float4 v = make_float4(0.f, 0.f, 0.f, 0.f);
        if (node < NN) v = reinterpret_cast<const float4*>(h)[(size_t)node * 32 + c4];
        *reinterpret_cast<float4*>(As + m * 132 + c4 * 4) = v;
    }
    stage_W(Ws, (const float4*)Wm1, 128);
    __syncthreads();

    int m0 = (TID >> 4) * 4, n0 = (TID & 15) * 8, cn = (TID & 15) * 2;
    u64 acc2[4][4];

    // P
#pragma unroll
    for (int i = 0; i < 4; ++i)
#pragma unroll
        for (int j = 0; j < 4; ++j) acc2[i][j] = 0ull;
    mm<128, 132>(As, Wu, acc2, m0, cn);
#pragma unroll
    for (int i = 0; i < 4; ++i) {
        int node = base + m0 + i;
        if (node < NN) {
            float2 f0 = unpk(acc2[i][0]), f1 = unpk(acc2[i][1]);
            float2 f2 = unpk(acc2[i][2]), f3 = unpk(acc2[i][3]);
            float4* p = (float4*)(g_P + (size_t)node * 128 + n0);
            p[0] = make_float4(f0.x, f0.y, f1.x, f1.y);
            p[1] = make_float4(f2.x, f2.y, f3.x, f3.y);
        }
    }
    __syncthreads();

    // Q (restage weights over same buffer)
    stage_W(Ws, (const float4*)(Wm1 + 128 * 128), 128);
    __syncthreads();
#pragma unroll
    for (int i = 0; i < 4; ++i)
#pragma unroll
        for (int j = 0; j < 4; ++j) acc2[i][j] = 0ull;
    mm<128, 132>(As, Wu, acc2, m0, cn);
#pragma unroll
    for (int i = 0; i < 4; ++i) {
        int node = base + m0 + i;
        if (node < NN) {
            float2 f0 = unpk(acc2[i][0]), f1 = unpk(acc2[i][1]);
            float2 f2 = unpk(acc2[i][2]), f3 = unpk(acc2[i][3]);
            float4* p = (float4*)(g_Q + (size_t)node * 128 + n0);
            p[0] = make_float4(f0.x, f0.y, f1.x, f1.y);
            p[1] = make_float4(f2.x, f2.y, f3.x, f3.y);
        }
    }
}

// ---------------------------------------------------------------------------
// Kernel 2: edge messages + scatter. 128 edges per block (EE/128 = 6250 exact).
// ---------------------------------------------------------------------------
#define EDGE_SMEM (128 * 132 * 4 + 128 * 36 * 4 + 32 * 32 * 16 + 128 * 32 * 16 + 128 * 8)
__global__ void __launch_bounds__(512, 1)
edge_kernel(const float* __restrict__ edge_attr,
            const float* __restrict__ Wm1, const float* __restrict__ bm1,
            const float* __restrict__ Wm2, const float* __restrict__ bm2) {
    extern __shared__ float sm[];
    float* As = sm;                                     // 128 x 132 (x_pre, then X)
    float* Es = As + 128 * 132;                         // 128 x 36
    float4* W1s = (float4*)(Es + 128 * 36);             // 32 x 32 cells
    float4* W2s = W1s + 32 * 32;                        // 128 x 32 cells
    int* ssrc = (int*)(W2s + 128 * 32);                 // 128
    int* sdst = ssrc + 128;                             // 128
    const ulonglong2* W1u = (const ulonglong2*)W1s;
    const ulonglong2* W2u = (const ulonglong2*)W2s;

    int base = blockIdx.x * 128;

    if (TID < 128) {
        ssrc[TID] = g_src[base + TID];
        sdst[TID] = g_dst[base + TID];
    }
    for (int s = TID; s < 128 * 8; s += 512) {
        int m = s >> 3, c = s & 7;
        *reinterpret_cast<float4*>(Es + m * 36 + c * 4) =
            reinterpret_cast<const float4*>(edge_attr)[(size_t)(base + m) * 8 + c];
    }
    stage_W(W1s, (const float4*)(Wm1 + 256 * 128), 32);
    stage_W(W2s, (const float4*)Wm2, 128);
    __syncthreads();

    // gather: As[e][:] = P[src] + Q[dst] + bm1
    for (int s = TID; s < 128 * 32; s += 512) {
        int m = s >> 5, c4 = s & 31;
        int sn = ssrc[m], dn = sdst[m];
        float4 p = reinterpret_cast<const float4*>(g_P)[(size_t)sn * 32 + c4];
        float4 q = reinterpret_cast<const float4*>(g_Q)[(size_t)dn * 32 + c4];
        float4 b = reinterpret_cast<const float4*>(bm1)[c4];
        *reinterpret_cast<float4*>(As + m * 132 + c4 * 4) =
            make_float4(p.x + q.x + b.x, p.y + q.y + b.y, p.z + q.z + b.z, p.w + q.w + b.w);
    }
    __syncthreads();

    int m0 = (TID >> 4) * 4, n0 = (TID & 15) * 8, cn = (TID & 15) * 2;
    u64 acc2[4][4];

    // GEMM0: X = relu(x_pre + Es @ Wm1c); acc init from own 4x8 tile of As
#pragma unroll
    for (int i = 0; i < 4; ++i) {
        const u64* row = (const u64*)(As + (m0 + i) * 132 + n0);
        acc2[i][0] = row[0]; acc2[i][1] = row[1];
        acc2[i][2] = row[2]; acc2[i][3] = row[3];
    }
    mm<32, 36>(Es, W1u, acc2, m0, cn);
    // relu + write X back to own 4x8 tile (same addresses: thread-private)
#pragma unroll
    for (int i = 0; i < 4; ++i) {
        float2 f0 = unpk(acc2[i][0]), f1 = unpk(acc2[i][1]);
        float2 f2 = unpk(acc2[i][2]), f3 = unpk(acc2[i][3]);
        float4* row = (float4*)(As + (m0 + i) * 132 + n0);
        row[0] = make_float4(fmaxf(f0.x, 0.f), fmaxf(f0.y, 0.f), fmaxf(f1.x, 0.f), fmaxf(f1.y, 0.f));
        row[1] = make_float4(fmaxf(f2.x, 0.f), fmaxf(f2.y, 0.f), fmaxf(f3.x, 0.f), fmaxf(f3.y, 0.f));
    }
    __syncthreads();

    // GEMM1: M = relu(X @ Wm2 + bm2)
    {
        u64 b0 = pack2(bm2[n0], bm2[n0 + 1]);
        u64 b1 = pack2(bm2[n0 + 2], bm2[n0 + 3]);
        u64 b2 = pack2(bm2[n0 + 4], bm2[n0 + 5]);
        u64 b3 = pack2(bm2[n0 + 6], bm2[n0 + 7]);
#pragma unroll
        for (int i = 0; i < 4; ++i) {
            acc2[i][0] = b0; acc2[i][1] = b1; acc2[i][2] = b2; acc2[i][3] = b3;
        }
    }
    mm<128, 132>(As, W2u, acc2, m0, cn);

    // relu + scatter-add
#pragma unroll
    for (int i = 0; i < 4; ++i) {
        float2 f0 = unpk(acc2[i][0]), f1 = unpk(acc2[i][1]);
        float2 f2 = unpk(acc2[i][2]), f3 = unpk(acc2[i][3]);
        int d = sdst[m0 + i];
        float* p = g_agg + (size_t)d * 128 + n0;
        red_add_v4(p, make_float4(fmaxf(f0.x, 0.f), fmaxf(f0.y, 0.f), fmaxf(f1.x, 0.f), fmaxf(f1.y, 0.f)));
        red_add_v4(p + 4, make_float4(fmaxf(f2.x, 0.f), fmaxf(f2.y, 0.f), fmaxf(f3.x, 0.f), fmaxf(f3.y, 0.f)));
    }
}

// ---------------------------------------------------------------------------
// Kernel 3: update.  u = relu([h,agg]@Wu1+bu1); out = h + u@Wu2 + bu2
// K=256 split into two 128-k phases (weight buffer restaged between).
// ---------------------------------------------------------------------------
#define UPD_SMEM (128 * 260 * 4 + 128 * 32 * 16)
__global__ void __launch_bounds__(512, 1)
update_kernel(const float* __restrict__ h,
              const float* __restrict__ Wu1, const float* __restrict__ bu1,
              const float* __restrict__ Wu2, const float* __restrict__ bu2,
              float* __restrict__ out) {
    extern __shared__ float sm[];
    float* As = sm;                                   // 128 x 260 ([h | agg]); later cols 0..127 hold U
    float4* Ws = (float4*)(sm + 128 * 260);           // 128 x 32 cells
    const ulonglong2* Wu = (const ulonglong2*)Ws;
    int base = blockIdx.x * 128;

    for (int s = TID; s < 128 * 64; s += 512) {
        int m = s >> 6, c = s & 63;
        int node = base + m;
        float4 v = make_float4(0.f, 0.f, 0.f, 0.f);
        if (node < NN)
            v = (c < 32) ? reinterpret_cast<const float4*>(h)[(size_t)node * 32 + c]
                         : reinterpret_cast<const float4*>(g_agg)[(size_t)node * 32 + (c - 32)];
        *reinterpret_cast<float4*>(As + m * 260 + c * 4) = v;
    }
    stage_W(Ws, (const float4*)Wu1, 128);
    __syncthreads();

    int m0 = (TID >> 4) * 4, n0 = (TID & 15) * 8, cn = (TID & 15) * 2;
    u64 acc2[4][4];

    // U = relu([h,agg]@Wu1 + bu1): phase 1 (h-part)
    {
        u64 b0 = pack2(bu1[n0], bu1[n0 + 1]);
        u64 b1 = pack2(bu1[n0 + 2], bu1[n0 + 3]);
        u64 b2 = pack2(bu1[n0 + 4], bu1[n0 + 5]);
        u64 b3 = pack2(bu1[n0 + 6], bu1[n0 + 7]);
#pragma unroll
        for (int i = 0; i < 4; ++i) {
            acc2[i][0] = b0; acc2[i][1] = b1; acc2[i][2] = b2; acc2[i][3] = b3;
        }
    }
    mm<128, 260>(As, Wu, acc2, m0, cn);
    __syncthreads();
    stage_W(Ws, (const float4*)(Wu1 + 128 * 128), 128);
    __syncthreads();
    mm<128, 260>(As + 128, Wu, acc2, m0, cn);   // phase 2 (agg-part, cols 128..255)

    // relu -> write U into As cols 0..127 (own tile; phase-2 readers use cols 128+)
#pragma unroll
    for (int i = 0; i < 4; ++i) {
        float2 f0 = unpk(acc2[i][0]), f1 = unpk(acc2[i][1]);
        float2 f2 = unpk(acc2[i][2]), f3 = unpk(acc2[i][3]);
        float4* row = (float4*)(As + (m0 + i) * 260 + n0);
        row[0] = make_float4(fmaxf(f0.x, 0.f), fmaxf(f0.y, 0.f), fmaxf(f1.x, 0.f), fmaxf(f1.y, 0.f));
        row[1] = make_float4(fmaxf(f2.x, 0.f), fmaxf(f2.y, 0.f), fmaxf(f3.x, 0.f), fmaxf(f3.y, 0.f));
    }
    __syncthreads();
    stage_W(Ws, (const float4*)Wu2, 128);
    __syncthreads();

    // out = h + U @ Wu2 + bu2
    {
        u64 b0 = pack2(bu2[n0], bu2[n0 + 1]);
        u64 b1 = pack2(bu2[n0 + 2], bu2[n0 + 3]);
        u64 b2 = pack2(bu2[n0 + 4], bu2[n0 + 5]);
        u64 b3 = pack2(bu2[n0 + 6], bu2[n0 + 7]);
#pragma unroll
        for (int i = 0; i < 4; ++i) {
            acc2[i][0] = b0; acc2[i][1] = b1; acc2[i][2] = b2; acc2[i][3] = b3;
        }
    }
    mm<128, 260>(As, Wu, acc2, m0, cn);
#pragma unroll
    for (int i = 0; i < 4; ++i) {
        int node = base + m0 + i;
        if (node < NN) {
            float2 f0 = unpk(acc2[i][0]), f1 = unpk(acc2[i][1]);
            float2 f2 = unpk(acc2[i][2]), f3 = unpk(acc2[i][3]);
            const float4* hp = (const float4*)(h + (size_t)node * 128 + n0);
            float4 h0 = hp[0], h1 = hp[1];
            float4* p = (float4*)(out + (size_t)node * 128 + n0);
            p[0] = make_float4(h0.x + f0.x, h0.y + f0.y, h0.z + f1.x, h0.w + f1.y);
            p[1] = make_float4(h1.x + f2.x, h1.y + f2.y, h1.z + f3.x, h1.w + f3.y);
        }
    }
}

// ---------------------------------------------------------------------------
extern "C" void kernel_launch(void* const* d_in, const int* in_sizes, int n_in,
                              void* d_out, int out_size) {
    const float* h         = (const float*)d_in[0];
    const float* edge_attr = (const float*)d_in[1];
    const float* Wm1       = (const float*)d_in[2];
    const float* bm1       = (const float*)d_in[3];
    const float* Wm2       = (const float*)d_in[4];
    const float* bm2       = (const float*)d_in[5];
    const float* Wu1       = (const float*)d_in[6];
    const float* bu1       = (const float*)d_in[7];
    const float* Wu2       = (const float*)d_in[8];
    const float* bu2       = (const float*)d_in[9];
    const void*  eidx      = (const void*)d_in[10];
    float* out             = (float*)d_out;

    cudaFuncSetAttribute(pq_kernel,     cudaFuncAttributeMaxDynamicSharedMemorySize, PQ_SMEM);
    cudaFuncSetAttribute(edge_kernel,   cudaFuncAttributeMaxDynamicSharedMemorySize, EDGE_SMEM);
    cudaFuncSetAttribute(update_kernel, cudaFuncAttributeMaxDynamicSharedMemorySize, UPD_SMEM);

    detect_idx_kernel<<<1, 32>>>(eidx);
    convert_idx_kernel<<<(EE + 255) / 256, 256>>>(eidx);
    zero_agg_kernel<<<(NN * 32 + 255) / 256, 256>>>();
    pq_kernel<<<(NN + 127) / 128, 512, PQ_SMEM>>>(h, Wm1);
    edge_kernel<<<EE / 128, 512, EDGE_SMEM>>>(edge_attr, Wm1, bm1, Wm2, bm2);
    update_kernel<<<(NN + 127) / 128, 512, UPD_SMEM>>>(h, Wu1, bu1, Wu2, bu2, out);
}

// round 8
// speedup vs baseline: 1.6653x; 1.5767x over previous
#include <cuda_runtime.h>
#include <cuda_bf16.h>

#define NN 50000
#define EE 800000
#define TID ((int)threadIdx.x)
typedef unsigned long long u64;
typedef unsigned int u32;
typedef unsigned short u16;

// ---------------- global scratch ----------------
__device__ float g_P[NN * 128];
__device__ float g_Q[NN * 128];
__device__ float g_agg[NN * 128];
__device__ int g_src[EE];
__device__ int g_dst[EE];
__device__ int g_mode;
// fragment-ordered bf16x2 weights for mma.sync B operands (hi/lo split)
#define W1F_U32 (2 * 2 * 16 * 32 * 2)    // ver, kc(2), ntile(16), lane(32), reg(2)
#define W2F_U32 (2 * 8 * 16 * 32 * 2)    // ver, kc(8), ntile(16), lane(32), reg(2)
__device__ u32 g_W1f[W1F_U32];
__device__ u32 g_W2f[W2F_U32];

// ---------------- helpers ----------------
__device__ __forceinline__ u16 f2bf(float x) { u16 h; asm("cvt.rn.bf16.f32 %0, %1;" : "=h"(h) : "f"(x)); return h; }
__device__ __forceinline__ float bfhi2f(u16 h) { return __uint_as_float((u32)h << 16); }
__device__ __forceinline__ void red_add_v2(float* addr, float x, float y) {
    asm volatile("red.global.add.v2.f32 [%0], {%1, %2};" :: "l"(addr), "f"(x), "f"(y) : "memory");
}
// split float pair -> packed bf16x2 hi and lo (lo = residual)
__device__ __forceinline__ void split2(float x, float y, u32& hi, u32& lo) {
    u16 h0 = f2bf(x), h1 = f2bf(y);
    u16 l0 = f2bf(x - bfhi2f(h0)), l1 = f2bf(y - bfhi2f(h1));
    hi = (u32)h0 | ((u32)h1 << 16);
    lo = (u32)l0 | ((u32)l1 << 16);
}
__device__ __forceinline__ void mma16816(float c[4], const u32 a[4], u32 b0, u32 b1) {
    asm("mma.sync.aligned.m16n8k16.row.col.f32.bf16.bf16.f32 "
        "{%0,%1,%2,%3}, {%4,%5,%6,%7}, {%8,%9}, {%0,%1,%2,%3};"
        : "+f"(c[0]), "+f"(c[1]), "+f"(c[2]), "+f"(c[3])
        : "r"(a[0]), "r"(a[1]), "r"(a[2]), "r"(a[3]), "r"(b0), "r"(b1));
}

// f32x2 FFMA2 helpers (pq/update SIMT kernels)
__device__ __forceinline__ u64 pack_dup(float x) { u64 r; asm("mov.b64 %0, {%1, %1};" : "=l"(r) : "f"(x)); return r; }
__device__ __forceinline__ u64 pack2(float x, float y) { u64 r; asm("mov.b64 %0, {%1, %2};" : "=l"(r) : "f"(x), "f"(y)); return r; }
__device__ __forceinline__ float2 unpk(u64 v) { float2 f; asm("mov.b64 {%0, %1}, %2;" : "=f"(f.x), "=f"(f.y) : "l"(v)); return f; }
__device__ __forceinline__ void ffma2(u64& d, u64 a, u64 b) { asm("fma.rn.f32x2 %0, %1, %2, %0;" : "+l"(d) : "l"(a), "l"(b)); }
__device__ __forceinline__ void red_add_v4(float* addr, float4 v) {
    asm volatile("red.global.add.v4.f32 [%0], {%1, %2, %3, %4};"
                 :: "l"(addr), "f"(v.x), "f"(v.y), "f"(v.z), "f"(v.w) : "memory");
}

// ---------------- index dtype detect / convert / zero ----------------
__global__ void detect_idx_kernel(const void* __restrict__ eidx) {
    if (TID == 0) {
        const long long* p = (const long long*)eidx;
        int ok = 1;
        for (int i = 0; i < 64; ++i) {
            long long v = p[i];
            if (v < 0 || v >= NN) { ok = 0; break; }
        }
        g_mode = ok;
    }
}
__global__ void convert_idx_kernel(const void* __restrict__ eidx) {
    int i = blockIdx.x * 256 + TID;
    if (i >= EE) return;
    if (g_mode) {
        const long long* p = (const long long*)eidx;
        g_src[i] = (int)p[i];
        g_dst[i] = (int)p[EE + i];
    } else {
        const int* p = (const int*)eidx;
        g_src[i] = p[i];
        g_dst[i] = p[EE + i];
    }
}
__global__ void zero_agg_kernel() {
    int i = blockIdx.x * 256 + TID;
    if (i < NN * 32)
        reinterpret_cast<float4*>(g_agg)[i] = make_float4(0.f, 0.f, 0.f, 0.f);
}

// ---------------- weight prep: fragment-ordered bf16 hi/lo ------------------
// B-frag (m16n8k16): reg0 = {B[k0][n], B[k0+1][n]}, reg1 = {B[k0+8][n], B[k0+9][n]}
// with k0 = kc*16 + (lane%4)*2, n = ntile*8 + lane/4.
__global__ void prep_w_kernel(const float* __restrict__ Wm1, const float* __restrict__ Wm2) {
    int i = blockIdx.x * 256 + TID;
    if (i < W1F_U32) {
        int r = i & 1, l = (i >> 1) & 31, t = (i >> 6) & 15, kc = (i >> 10) & 1, ver = (i >> 11) & 1;
        int k0 = kc * 16 + (l & 3) * 2 + r * 8;
        int n = t * 8 + (l >> 2);
        float v0 = Wm1[(256 + k0) * 128 + n];
        float v1 = Wm1[(256 + k0 + 1) * 128 + n];
        u16 h0 = f2bf(v0), h1 = f2bf(v1);
        u32 out;
        if (ver == 0) out = (u32)h0 | ((u32)h1 << 16);
        else {
            u16 l0 = f2bf(v0 - bfhi2f(h0)), l1 = f2bf(v1 - bfhi2f(h1));
            out = (u32)l0 | ((u32)l1 << 16);
        }
        g_W1f[i] = out;
    } else if (i < W1F_U32 + W2F_U32) {
        int j = i - W1F_U32;
        int r = j & 1, l = (j >> 1) & 31, t = (j >> 6) & 15, kc = (j >> 10) & 7, ver = (j >> 13) & 1;
        int k0 = kc * 16 + (l & 3) * 2 + r * 8;
        int n = t * 8 + (l >> 2);
        float v0 = Wm2[k0 * 128 + n];
        float v1 = Wm2[(k0 + 1) * 128 + n];
        u16 h0 = f2bf(v0), h1 = f2bf(v1);
        u32 out;
        if (ver == 0) out = (u32)h0 | ((u32)h1 << 16);
        else {
            u16 l0 = f2bf(v0 - bfhi2f(h0)), l1 = f2bf(v1 - bfhi2f(h1));
            out = (u32)l0 | ((u32)l1 << 16);
        }
        g_W2f[j] = out;
    }
}

// ---------------- edge kernel (mma.sync bf16x3) -----------------------------
// 128 edges/block, 256 threads, warp w owns rows w*16..w*16+15, all 128 cols.
#define EDGE_SMEM_B (256 * 4 + W1F_U32 * 4 + W2F_U32 * 4)
__global__ void __launch_bounds__(256, 2)
edge_kernel(const float* __restrict__ edge_attr,
            const float* __restrict__ bm1, const float* __restrict__ bm2) {
    extern __shared__ u32 smu[];
    int* ssrc = (int*)smu;            // 128
    int* sdst = ssrc + 128;           // 128
    u32* W1s = smu + 256;             // 4096 u32
    u32* W2s = W1s + W1F_U32;         // 16384 u32

    int w = TID >> 5, l = TID & 31;
    int base = blockIdx.x * 128;

    if (TID < 128) {
        ssrc[TID] = g_src[base + TID];
        sdst[TID] = g_dst[base + TID];
    }
    {
        float4* d1 = (float4*)W1s; const float4* s1 = (const float4*)g_W1f;
        for (int i = TID; i < W1F_U32 / 4; i += 256) d1[i] = s1[i];
        float4* d2 = (float4*)W2s; const float4* s2 = (const float4*)g_W2f;
        for (int i = TID; i < W2F_U32 / 4; i += 256) d2[i] = s2[i];
    }
    __syncthreads();

    int g = l >> 2;          // group row within 16-row tile
    int q = (l & 3) * 2;     // col/k pair offset
    int r0 = w * 16 + g;     // local edge rows this thread touches
    int r1 = r0 + 8;

    // ---- A-fragments for GEMM0 from edge_attr (bf16 split) ----
    u32 Eh[2][4], El[2][4];
    {
        const float* ra = edge_attr + (size_t)(base + r0) * 32;
        const float* rb = edge_attr + (size_t)(base + r1) * 32;
#pragma unroll
        for (int kc = 0; kc < 2; ++kc) {
            float2 f0 = *(const float2*)(ra + kc * 16 + q);
            float2 f1 = *(const float2*)(rb + kc * 16 + q);
            float2 f2v = *(const float2*)(ra + kc * 16 + q + 8);
            float2 f3 = *(const float2*)(rb + kc * 16 + q + 8);
            split2(f0.x, f0.y, Eh[kc][0], El[kc][0]);
            split2(f1.x, f1.y, Eh[kc][1], El[kc][1]);
            split2(f2v.x, f2v.y, Eh[kc][2], El[kc][2]);
            split2(f3.x, f3.y, Eh[kc][3], El[kc][3]);
        }
    }

    // ---- C init: x_pre = P[src] + Q[dst] + bm1, directly in accumulator layout ----
    float C[16][4];
    int s0 = ssrc[r0], s1 = ssrc[r1], d0 = sdst[r0], d1 = sdst[r1];
    const float* P0 = g_P + (size_t)s0 * 128;
    const float* P1 = g_P + (size_t)s1 * 128;
    const float* Q0 = g_Q + (size_t)d0 * 128;
    const float* Q1 = g_Q + (size_t)d1 * 128;
#pragma unroll
    for (int t = 0; t < 16; ++t) {
        int c = t * 8 + q;
        float2 b = *(const float2*)(bm1 + c);
        float2 p0 = *(const float2*)(P0 + c), q0 = *(const float2*)(Q0 + c);
        float2 p1 = *(const float2*)(P1 + c), q1 = *(const float2*)(Q1 + c);
        C[t][0] = p0.x + q0.x + b.x; C[t][1] = p0.y + q0.y + b.y;
        C[t][2] = p1.x + q1.x + b.x; C[t][3] = p1.y + q1.y + b.y;
    }

    // ---- GEMM0: C += E @ W1c^T, 3 split passes ----
#pragma unroll
    for (int p = 0; p < 3; ++p) {
        const u32 (*A)[4] = (p == 1) ? El : Eh;
        int ver = (p == 2) ? 1 : 0;
#pragma unroll
        for (int kc = 0; kc < 2; ++kc)
#pragma unroll
            for (int t = 0; t < 16; ++t) {
                uint2 bv = *(const uint2*)(W1s + ((((ver * 2 + kc) * 16 + t) * 32 + l) * 2));
                mma16816(C[t], A[kc], bv.x, bv.y);
            }
    }

    // ---- epilogue 1: X = relu(C); split to GEMM1 A-fragments (identity map) ----
    u32 Ah[8][4], Al[8][4];
#pragma unroll
    for (int kc = 0; kc < 8; ++kc) {
        split2(fmaxf(C[2 * kc][0], 0.f),     fmaxf(C[2 * kc][1], 0.f),     Ah[kc][0], Al[kc][0]);
        split2(fmaxf(C[2 * kc][2], 0.f),     fmaxf(C[2 * kc][3], 0.f),     Ah[kc][1], Al[kc][1]);
        split2(fmaxf(C[2 * kc + 1][0], 0.f), fmaxf(C[2 * kc + 1][1], 0.f), Ah[kc][2], Al[kc][2]);
        split2(fmaxf(C[2 * kc + 1][2], 0.f), fmaxf(C[2 * kc + 1][3], 0.f), Ah[kc][3], Al[kc][3]);
    }

    // ---- GEMM1: M = relu(X @ Wm2^T + bm2), two N-halves; scatter-add ----
    float* agg0 = g_agg + (size_t)d0 * 128;
    float* agg1 = g_agg + (size_t)d1 * 128;
#pragma unroll
    for (int hf = 0; hf < 2; ++hf) {
        float C2[8][4];
#pragma unroll
        for (int t = 0; t < 8; ++t) {
            float2 b = *(const float2*)(bm2 + hf * 64 + t * 8 + q);
            C2[t][0] = b.x; C2[t][1] = b.y; C2[t][2] = b.x; C2[t][3] = b.y;
        }
#pragma unroll
        for (int p = 0; p < 3; ++p) {
            const u32 (*A)[4] = (p == 1) ? Al : Ah;
            int ver = (p == 2) ? 1 : 0;
#pragma unroll
            for (int kc = 0; kc < 8; ++kc)
#pragma unroll
                for (int t = 0; t < 8; ++t) {
                    int tt = hf * 8 + t;
                    uint2 bv = *(const uint2*)(W2s + ((((ver * 8 + kc) * 16 + tt) * 32 + l) * 2));
                    mma16816(C2[t], A[kc], bv.x, bv.y);
                }
        }
#pragma unroll
        for (int t = 0; t < 8; ++t) {
            int c = hf * 64 + t * 8 + q;
            red_add_v2(agg0 + c, fmaxf(C2[t][0], 0.f), fmaxf(C2[t][1], 0.f));
            red_add_v2(agg1 + c, fmaxf(C2[t][2], 0.f), fmaxf(C2[t][3], 0.f));
        }
    }
}

// ---------------- FFMA2 SIMT GEMM (pq / update, unchanged from R4) ----------
__device__ __forceinline__ void stage_W(float4* dst, const float4* __restrict__ src, int krows) {
    for (int s = TID; s < (krows << 5); s += 512) {
        int k = s >> 5, c = s & 31;
        dst[(k << 5) + (c ^ (k & 31))] = src[s];
    }
}
template<int K, int AST>
__device__ __forceinline__ void mm(const float* __restrict__ As,
                                   const ulonglong2* __restrict__ Bu,
                                   u64 acc2[4][4], int m0, int cn) {
#pragma unroll 4
    for (int k = 0; k < K; ++k) {
        int sw = k & 31;
        int kb = k << 5;
        ulonglong2 p0 = Bu[kb + (cn ^ sw)];
        ulonglong2 p1 = Bu[kb + ((cn ^ sw) ^ 1)];
#pragma unroll
        for (int i = 0; i < 4; ++i) {
            u64 a = pack_dup(As[(m0 + i) * AST + k]);
            ffma2(acc2[i][0], a, p0.x);
            ffma2(acc2[i][1], a, p0.y);
            ffma2(acc2[i][2], a, p1.x);
            ffma2(acc2[i][3], a, p1.y);
        }
    }
}

#define PQ_SMEM (128 * 132 * 4 + 128 * 32 * 16)
__global__ void __launch_bounds__(512, 1)
pq_kernel(const float* __restrict__ h, const float* __restrict__ Wm1) {
    extern __shared__ float sm[];
    float* As = sm;
    float4* Ws = (float4*)(sm + 128 * 132);
    const ulonglong2* Wu = (const ulonglong2*)Ws;
    int base = blockIdx.x * 128;

    for (int s = TID; s < 128 * 32; s += 512) {
        int m = s >> 5, c4 = s & 31;
        int node = base + m;
        float4 v = make_float4(0.f, 0.f, 0.f, 0.f);
        if (node < NN) v = reinterpret_cast<const float4*>(h)[(size_t)node * 32 + c4];
        *reinterpret_cast<float4*>(As + m * 132 + c4 * 4) = v;
    }
    stage_W(Ws, (const float4*)Wm1, 128);
    __syncthreads();

    int m0 = (TID >> 4) * 4, n0 = (TID & 15) * 8, cn = (TID & 15) * 2;
    u64 acc2[4][4];
#pragma unroll
    for (int i = 0; i < 4; ++i)
#pragma unroll
        for (int j = 0; j < 4; ++j) acc2[i][j] = 0ull;
    mm<128, 132>(As, Wu, acc2, m0, cn);
#pragma unroll
    for (int i = 0; i < 4; ++i) {
        int node = base + m0 + i;
        if (node < NN) {
            float2 f0 = unpk(acc2[i][0]), f1 = unpk(acc2[i][1]);
            float2 f2 = unpk(acc2[i][2]), f3 = unpk(acc2[i][3]);
            float4* p = (float4*)(g_P + (size_t)node * 128 + n0);
            p[0] = make_float4(f0.x, f0.y, f1.x, f1.y);
            p[1] = make_float4(f2.x, f2.y, f3.x, f3.y);
        }
    }
    __syncthreads();
    stage_W(Ws, (const float4*)(Wm1 + 128 * 128), 128);
    __syncthreads();
#pragma unroll
    for (int i = 0; i < 4; ++i)
#pragma unroll
        for (int j = 0; j < 4; ++j) acc2[i][j] = 0ull;
    mm<128, 132>(As, Wu, acc2, m0, cn);
#pragma unroll
    for (int i = 0; i < 4; ++i) {
        int node = base + m0 + i;
        if (node < NN) {
            float2 f0 = unpk(acc2[i][0]), f1 = unpk(acc2[i][1]);
            float2 f2 = unpk(acc2[i][2]), f3 = unpk(acc2[i][3]);
            float4* p = (float4*)(g_Q + (size_t)node * 128 + n0);
            p[0] = make_float4(f0.x, f0.y, f1.x, f1.y);
            p[1] = make_float4(f2.x, f2.y, f3.x, f3.y);
        }
    }
}

#define UPD_SMEM (128 * 260 * 4 + 128 * 32 * 16)
__global__ void __launch_bounds__(512, 1)
update_kernel(const float* __restrict__ h,
              const float* __restrict__ Wu1, const float* __restrict__ bu1,
              const float* __restrict__ Wu2, const float* __restrict__ bu2,
              float* __restrict__ out) {
    extern __shared__ float sm[];
    float* As = sm;
    float4* Ws = (float4*)(sm + 128 * 260);
    const ulonglong2* Wu = (const ulonglong2*)Ws;
    int base = blockIdx.x * 128;

    for (int s = TID; s < 128 * 64; s += 512) {
        int m = s >> 6, c = s & 63;
        int node = base + m;
        float4 v = make_float4(0.f, 0.f, 0.f, 0.f);
        if (node < NN)
            v = (c < 32) ? reinterpret_cast<const float4*>(h)[(size_t)node * 32 + c]
                         : reinterpret_cast<const float4*>(g_agg)[(size_t)node * 32 + (c - 32)];
        *reinterpret_cast<float4*>(As + m * 260 + c * 4) = v;
    }
    stage_W(Ws, (const float4*)Wu1, 128);
    __syncthreads();

    int m0 = (TID >> 4) * 4, n0 = (TID & 15) * 8, cn = (TID & 15) * 2;
    u64 acc2[4][4];
    {
        u64 b0 = pack2(bu1[n0], bu1[n0 + 1]);
        u64 b1 = pack2(bu1[n0 + 2], bu1[n0 + 3]);
        u64 b2 = pack2(bu1[n0 + 4], bu1[n0 + 5]);
        u64 b3 = pack2(bu1[n0 + 6], bu1[n0 + 7]);
#pragma unroll
        for (int i = 0; i < 4; ++i) { acc2[i][0] = b0; acc2[i][1] = b1; acc2[i][2] = b2; acc2[i][3] = b3; }
    }
    mm<128, 260>(As, Wu, acc2, m0, cn);
    __syncthreads();
    stage_W(Ws, (const float4*)(Wu1 + 128 * 128), 128);
    __syncthreads();
    mm<128, 260>(As + 128, Wu, acc2, m0, cn);
#pragma unroll
    for (int i = 0; i < 4; ++i) {
        float2 f0 = unpk(acc2[i][0]), f1 = unpk(acc2[i][1]);
        float2 f2 = unpk(acc2[i][2]), f3 = unpk(acc2[i][3]);
        float4* row = (float4*)(As + (m0 + i) * 260 + n0);
        row[0] = make_float4(fmaxf(f0.x, 0.f), fmaxf(f0.y, 0.f), fmaxf(f1.x, 0.f), fmaxf(f1.y, 0.f));
        row[1] = make_float4(fmaxf(f2.x, 0.f), fmaxf(f2.y, 0.f), fmaxf(f3.x, 0.f), fmaxf(f3.y, 0.f));
    }
    __syncthreads();
    stage_W(Ws, (const float4*)Wu2, 128);
    __syncthreads();
    {
        u64 b0 = pack2(bu2[n0], bu2[n0 + 1]);
        u64 b1 = pack2(bu2[n0 + 2], bu2[n0 + 3]);
        u64 b2 = pack2(bu2[n0 + 4], bu2[n0 + 5]);
        u64 b3 = pack2(bu2[n0 + 6], bu2[n0 + 7]);
#pragma unroll
        for (int i = 0; i < 4; ++i) { acc2[i][0] = b0; acc2[i][1] = b1; acc2[i][2] = b2; acc2[i][3] = b3; }
    }
    mm<128, 260>(As, Wu, acc2, m0, cn);
#pragma unroll
    for (int i = 0; i < 4; ++i) {
        int node = base + m0 + i;
        if (node < NN) {
            float2 f0 = unpk(acc2[i][0]), f1 = unpk(acc2[i][1]);
            float2 f2 = unpk(acc2[i][2]), f3 = unpk(acc2[i][3]);
            const float4* hp = (const float4*)(h + (size_t)node * 128 + n0);
            float4 h0 = hp[0], h1 = hp[1];
            float4* p = (float4*)(out + (size_t)node * 128 + n0);
            p[0] = make_float4(h0.x + f0.x, h0.y + f0.y, h0.z + f1.x, h0.w + f1.y);
            p[1] = make_float4(h1.x + f2.x, h1.y + f2.y, h1.z + f3.x, h1.w + f3.y);
        }
    }
}

// ---------------------------------------------------------------------------
extern "C" void kernel_launch(void* const* d_in, const int* in_sizes, int n_in,
                              void* d_out, int out_size) {
    const float* h         = (const float*)d_in[0];
    const float* edge_attr = (const float*)d_in[1];
    const float* Wm1       = (const float*)d_in[2];
    const float* bm1       = (const float*)d_in[3];
    const float* Wm2       = (const float*)d_in[4];
    const float* bm2       = (const float*)d_in[5];
    const float* Wu1       = (const float*)d_in[6];
    const float* bu1       = (const float*)d_in[7];
    const float* Wu2       = (const float*)d_in[8];
    const float* bu2       = (const float*)d_in[9];
    const void*  eidx      = (const void*)d_in[10];
    float* out             = (float*)d_out;

    cudaFuncSetAttribute(pq_kernel,     cudaFuncAttributeMaxDynamicSharedMemorySize, PQ_SMEM);
    cudaFuncSetAttribute(edge_kernel,   cudaFuncAttributeMaxDynamicSharedMemorySize, EDGE_SMEM_B);
    cudaFuncSetAttribute(update_kernel, cudaFuncAttributeMaxDynamicSharedMemorySize, UPD_SMEM);

    detect_idx_kernel<<<1, 32>>>(eidx);
    convert_idx_kernel<<<(EE + 255) / 256, 256>>>(eidx);
    zero_agg_kernel<<<(NN * 32 + 255) / 256, 256>>>();
    prep_w_kernel<<<(W1F_U32 + W2F_U32 + 255) / 256, 256>>>(Wm1, Wm2);
    pq_kernel<<<(NN + 127) / 128, 512, PQ_SMEM>>>(h, Wm1);
    edge_kernel<<<EE / 128, 256, EDGE_SMEM_B>>>(edge_attr, bm1, bm2);
    update_kernel<<<(NN + 127) / 128, 512, UPD_SMEM>>>(h, Wu1, bu1, Wu2, bu2, out);
}

// round 9
// speedup vs baseline: 2.1126x; 1.2686x over previous
#include <cuda_runtime.h>
#include <cuda_bf16.h>

#define NN 50000
#define EE 800000
#define TID ((int)threadIdx.x)
typedef unsigned long long u64;
typedef unsigned int u32;
typedef unsigned short u16;

// ---------------- global scratch ----------------
__device__ float g_P[NN * 128];
__device__ float g_Q[NN * 128];
__device__ float g_agg[NN * 128];
__device__ int g_src[EE];
__device__ int g_dst[EE];
__device__ int g_mode;
// fragment-ordered bf16x2 weights (hi/lo split) for mma.sync B operands
#define W1F_U32 (2 * 2 * 16 * 32 * 2)     // edge Wm1c:  ver, kc(2),  t(16), lane(32), r(2)
#define W2F_U32 (2 * 8 * 16 * 32 * 2)     // edge Wm2:   ver, kc(8),  ...
#define WPQ_U32 (2 * 8 * 16 * 32 * 2)     // Wm1a / Wm1b
#define WU1_U32 (2 * 16 * 16 * 32 * 2)    // Wu1: kc(16)
#define WU2_U32 (2 * 8 * 16 * 32 * 2)     // Wu2
__device__ u32 g_W1f[W1F_U32];
__device__ u32 g_W2f[W2F_U32];
__device__ u32 g_WPf[WPQ_U32];
__device__ u32 g_WQf[WPQ_U32];
__device__ u32 g_WU1f[WU1_U32];
__device__ u32 g_WU2f[WU2_U32];

// ---------------- helpers ----------------
__device__ __forceinline__ u16 f2bf(float x) { u16 h; asm("cvt.rn.bf16.f32 %0, %1;" : "=h"(h) : "f"(x)); return h; }
__device__ __forceinline__ float bfhi2f(u16 h) { return __uint_as_float((u32)h << 16); }
__device__ __forceinline__ void red_add_v2(float* addr, float x, float y) {
    asm volatile("red.global.add.v2.f32 [%0], {%1, %2};" :: "l"(addr), "f"(x), "f"(y) : "memory");
}
__device__ __forceinline__ void split2(float x, float y, u32& hi, u32& lo) {
    u16 h0 = f2bf(x), h1 = f2bf(y);
    u16 l0 = f2bf(x - bfhi2f(h0)), l1 = f2bf(y - bfhi2f(h1));
    hi = (u32)h0 | ((u32)h1 << 16);
    lo = (u32)l0 | ((u32)l1 << 16);
}
__device__ __forceinline__ void mma16816(float c[4], const u32 a[4], u32 b0, u32 b1) {
    asm("mma.sync.aligned.m16n8k16.row.col.f32.bf16.bf16.f32 "
        "{%0,%1,%2,%3}, {%4,%5,%6,%7}, {%8,%9}, {%0,%1,%2,%3};"
        : "+f"(c[0]), "+f"(c[1]), "+f"(c[2]), "+f"(c[3])
        : "r"(a[0]), "r"(a[1]), "r"(a[2]), "r"(a[3]), "r"(b0), "r"(b1));
}

// ---------------- index dtype detect / convert / zero ----------------
__global__ void detect_idx_kernel(const void* __restrict__ eidx) {
    if (TID == 0) {
        const long long* p = (const long long*)eidx;
        int ok = 1;
        for (int i = 0; i < 64; ++i) {
            long long v = p[i];
            if (v < 0 || v >= NN) { ok = 0; break; }
        }
        g_mode = ok;
    }
}
__global__ void convert_idx_kernel(const void* __restrict__ eidx) {
    int i = blockIdx.x * 256 + TID;
    if (i >= EE) return;
    if (g_mode) {
        const long long* p = (const long long*)eidx;
        g_src[i] = (int)p[i];
        g_dst[i] = (int)p[EE + i];
    } else {
        const int* p = (const int*)eidx;
        g_src[i] = p[i];
        g_dst[i] = p[EE + i];
    }
}
__global__ void zero_agg_kernel() {
    int i = blockIdx.x * 256 + TID;
    if (i < NN * 32)
        reinterpret_cast<float4*>(g_agg)[i] = make_float4(0.f, 0.f, 0.f, 0.f);
}

// ---------------- weight prep: fragment-ordered bf16 hi/lo ------------------
// B-frag (m16n8k16): reg r covers k0 = kc*16 + (lane%4)*2 + r*8, n = t*8 + lane/4.
__device__ __forceinline__ void prep_range(u32* dst, const float* __restrict__ Wsrc, int KC, int idx) {
    int r = idx & 1, l = (idx >> 1) & 31, t = (idx >> 6) & 15;
    int kc = (idx >> 10) % KC, ver = (idx >> 10) / KC;
    int k0 = kc * 16 + (l & 3) * 2 + r * 8;
    int n = t * 8 + (l >> 2);
    float v0 = Wsrc[k0 * 128 + n];
    float v1 = Wsrc[(k0 + 1) * 128 + n];
    u32 hi, lo; split2(v0, v1, hi, lo);
    dst[idx] = ver ? lo : hi;
}
#define PREP_TOTAL (W1F_U32 + W2F_U32 + 2 * WPQ_U32 + WU1_U32 + WU2_U32)
__global__ void prep_w_kernel(const float* __restrict__ Wm1, const float* __restrict__ Wm2,
                              const float* __restrict__ Wu1, const float* __restrict__ Wu2) {
    int i = blockIdx.x * 256 + TID;
    if (i < W1F_U32) { prep_range(g_W1f, Wm1 + 256 * 128, 2, i); return; }
    i -= W1F_U32;
    if (i < W2F_U32) { prep_range(g_W2f, Wm2, 8, i); return; }
    i -= W2F_U32;
    if (i < WPQ_U32) { prep_range(g_WPf, Wm1, 8, i); return; }
    i -= WPQ_U32;
    if (i < WPQ_U32) { prep_range(g_WQf, Wm1 + 128 * 128, 8, i); return; }
    i -= WPQ_U32;
    if (i < WU1_U32) { prep_range(g_WU1f, Wu1, 16, i); return; }
    i -= WU1_U32;
    if (i < WU2_U32) { prep_range(g_WU2f, Wu2, 8, i); return; }
}

// ---------------- edge kernel (mma.sync bf16x3) -- unchanged from R8 --------
#define EDGE_SMEM_B (256 * 4 + W1F_U32 * 4 + W2F_U32 * 4)
__global__ void __launch_bounds__(256, 2)
edge_kernel(const float* __restrict__ edge_attr,
            const float* __restrict__ bm1, const float* __restrict__ bm2) {
    extern __shared__ u32 smu[];
    int* ssrc = (int*)smu;
    int* sdst = ssrc + 128;
    u32* W1s = smu + 256;
    u32* W2s = W1s + W1F_U32;

    int w = TID >> 5, l = TID & 31;
    int base = blockIdx.x * 128;

    if (TID < 128) {
        ssrc[TID] = g_src[base + TID];
        sdst[TID] = g_dst[base + TID];
    }
    {
        float4* d1 = (float4*)W1s; const float4* s1 = (const float4*)g_W1f;
        for (int i = TID; i < W1F_U32 / 4; i += 256) d1[i] = s1[i];
        float4* d2 = (float4*)W2s; const float4* s2 = (const float4*)g_W2f;
        for (int i = TID; i < W2F_U32 / 4; i += 256) d2[i] = s2[i];
    }
    __syncthreads();

    int g = l >> 2;
    int q = (l & 3) * 2;
    int r0 = w * 16 + g;
    int r1 = r0 + 8;

    u32 Eh[2][4], El[2][4];
    {
        const float* ra = edge_attr + (size_t)(base + r0) * 32;
        const float* rb = edge_attr + (size_t)(base + r1) * 32;
#pragma unroll
        for (int kc = 0; kc < 2; ++kc) {
            float2 f0 = *(const float2*)(ra + kc * 16 + q);
            float2 f1 = *(const float2*)(rb + kc * 16 + q);
            float2 f2v = *(const float2*)(ra + kc * 16 + q + 8);
            float2 f3 = *(const float2*)(rb + kc * 16 + q + 8);
            split2(f0.x, f0.y, Eh[kc][0], El[kc][0]);
            split2(f1.x, f1.y, Eh[kc][1], El[kc][1]);
            split2(f2v.x, f2v.y, Eh[kc][2], El[kc][2]);
            split2(f3.x, f3.y, Eh[kc][3], El[kc][3]);
        }
    }

    float C[16][4];
    int s0 = ssrc[r0], s1 = ssrc[r1], d0 = sdst[r0], d1 = sdst[r1];
    const float* P0 = g_P + (size_t)s0 * 128;
    const float* P1 = g_P + (size_t)s1 * 128;
    const float* Q0 = g_Q + (size_t)d0 * 128;
    const float* Q1 = g_Q + (size_t)d1 * 128;
#pragma unroll
    for (int t = 0; t < 16; ++t) {
        int c = t * 8 + q;
        float2 b = *(const float2*)(bm1 + c);
        float2 p0 = *(const float2*)(P0 + c), q0 = *(const float2*)(Q0 + c);
        float2 p1 = *(const float2*)(P1 + c), q1 = *(const float2*)(Q1 + c);
        C[t][0] = p0.x + q0.x + b.x; C[t][1] = p0.y + q0.y + b.y;
        C[t][2] = p1.x + q1.x + b.x; C[t][3] = p1.y + q1.y + b.y;
    }

#pragma unroll
    for (int p = 0; p < 3; ++p) {
        const u32 (*A)[4] = (p == 1) ? El : Eh;
        int ver = (p == 2) ? 1 : 0;
#pragma unroll
        for (int kc = 0; kc < 2; ++kc)
#pragma unroll
            for (int t = 0; t < 16; ++t) {
                uint2 bv = *(const uint2*)(W1s + ((((ver * 2 + kc) * 16 + t) * 32 + l) * 2));
                mma16816(C[t], A[kc], bv.x, bv.y);
            }
    }

    u32 Ah[8][4], Al[8][4];
#pragma unroll
    for (int kc = 0; kc < 8; ++kc) {
        split2(fmaxf(C[2 * kc][0], 0.f),     fmaxf(C[2 * kc][1], 0.f),     Ah[kc][0], Al[kc][0]);
        split2(fmaxf(C[2 * kc][2], 0.f),     fmaxf(C[2 * kc][3], 0.f),     Ah[kc][1], Al[kc][1]);
        split2(fmaxf(C[2 * kc + 1][0], 0.f), fmaxf(C[2 * kc + 1][1], 0.f), Ah[kc][2], Al[kc][2]);
        split2(fmaxf(C[2 * kc + 1][2], 0.f), fmaxf(C[2 * kc + 1][3], 0.f), Ah[kc][3], Al[kc][3]);
    }

    float* agg0 = g_agg + (size_t)d0 * 128;
    float* agg1 = g_agg + (size_t)d1 * 128;
#pragma unroll
    for (int hf = 0; hf < 2; ++hf) {
        float C2[8][4];
#pragma unroll
        for (int t = 0; t < 8; ++t) {
            float2 b = *(const float2*)(bm2 + hf * 64 + t * 8 + q);
            C2[t][0] = b.x; C2[t][1] = b.y; C2[t][2] = b.x; C2[t][3] = b.y;
        }
#pragma unroll
        for (int p = 0; p < 3; ++p) {
            const u32 (*A)[4] = (p == 1) ? Al : Ah;
            int ver = (p == 2) ? 1 : 0;
#pragma unroll
            for (int kc = 0; kc < 8; ++kc)
#pragma unroll
                for (int t = 0; t < 8; ++t) {
                    int tt = hf * 8 + t;
                    uint2 bv = *(const uint2*)(W2s + ((((ver * 8 + kc) * 16 + tt) * 32 + l) * 2));
                    mma16816(C2[t], A[kc], bv.x, bv.y);
                }
        }
#pragma unroll
        for (int t = 0; t < 8; ++t) {
            int c = hf * 64 + t * 8 + q;
            red_add_v2(agg0 + c, fmaxf(C2[t][0], 0.f), fmaxf(C2[t][1], 0.f));
            red_add_v2(agg1 + c, fmaxf(C2[t][2], 0.f), fmaxf(C2[t][3], 0.f));
        }
    }
}

// ---------------- pq kernel (mma.sync): P = h@Wm1a, Q = h@Wm1b ---------------
#define PQ2_SMEM (WPQ_U32 * 4)
__global__ void __launch_bounds__(256, 2)
pq_kernel(const float* __restrict__ h) {
    extern __shared__ u32 smw[];
    int w = TID >> 5, l = TID & 31;
    int base = blockIdx.x * 128;
    int g = l >> 2, q = (l & 3) * 2;
    int r0 = base + w * 16 + g, r1 = r0 + 8;
    bool v0 = r0 < NN, v1 = r1 < NN;

    // A-fragments from h (loaded once, reused for P and Q)
    u32 Ah[8][4], Al[8][4];
    {
        const float* ra = h + (size_t)r0 * 128;
        const float* rb = h + (size_t)r1 * 128;
        float2 z = make_float2(0.f, 0.f);
#pragma unroll
        for (int kc = 0; kc < 8; ++kc) {
            float2 a0 = v0 ? *(const float2*)(ra + kc * 16 + q) : z;
            float2 a1 = v1 ? *(const float2*)(rb + kc * 16 + q) : z;
            float2 a2 = v0 ? *(const float2*)(ra + kc * 16 + q + 8) : z;
            float2 a3 = v1 ? *(const float2*)(rb + kc * 16 + q + 8) : z;
            split2(a0.x, a0.y, Ah[kc][0], Al[kc][0]);
            split2(a1.x, a1.y, Ah[kc][1], Al[kc][1]);
            split2(a2.x, a2.y, Ah[kc][2], Al[kc][2]);
            split2(a3.x, a3.y, Ah[kc][3], Al[kc][3]);
        }
    }

#pragma unroll 1
    for (int m = 0; m < 2; ++m) {
        if (m) __syncthreads();
        {
            const float4* s = (const float4*)(m ? g_WQf : g_WPf);
            float4* d = (float4*)smw;
            for (int i = TID; i < WPQ_U32 / 4; i += 256) d[i] = s[i];
        }
        __syncthreads();
        float* dst = m ? g_Q : g_P;
#pragma unroll
        for (int hf = 0; hf < 2; ++hf) {
            float C[8][4];
#pragma unroll
            for (int t = 0; t < 8; ++t) { C[t][0] = C[t][1] = C[t][2] = C[t][3] = 0.f; }
#pragma unroll
            for (int p = 0; p < 3; ++p) {
                const u32 (*A)[4] = (p == 1) ? Al : Ah;
                int ver = (p == 2) ? 1 : 0;
#pragma unroll
                for (int kc = 0; kc < 8; ++kc)
#pragma unroll
                    for (int t = 0; t < 8; ++t) {
                        int tt = hf * 8 + t;
                        uint2 bv = *(const uint2*)(smw + ((((ver * 8 + kc) * 16 + tt) * 32 + l) * 2));
                        mma16816(C[t], A[kc], bv.x, bv.y);
                    }
            }
#pragma unroll
            for (int t = 0; t < 8; ++t) {
                int c = hf * 64 + t * 8 + q;
                if (v0) *(float2*)(dst + (size_t)r0 * 128 + c) = make_float2(C[t][0], C[t][1]);
                if (v1) *(float2*)(dst + (size_t)r1 * 128 + c) = make_float2(C[t][2], C[t][3]);
            }
        }
    }
}

// ---------------- update kernel (mma.sync) ----------------------------------
// u = relu([h|agg] @ Wu1 + bu1);  out = h + u @ Wu2 + bu2
#define UPD2_SMEM (WU1_U32 * 4)   // 128 KB; WU2 restaged into first half later
__global__ void __launch_bounds__(256, 1)
update_kernel(const float* __restrict__ h,
              const float* __restrict__ bu1, const float* __restrict__ bu2,
              float* __restrict__ out) {
    extern __shared__ u32 smw[];
    int w = TID >> 5, l = TID & 31;
    int base = blockIdx.x * 128;
    int g = l >> 2, q = (l & 3) * 2;
    int r0 = base + w * 16 + g, r1 = r0 + 8;
    bool v0 = r0 < NN, v1 = r1 < NN;

    {
        const float4* s = (const float4*)g_WU1f;
        float4* d = (float4*)smw;
        for (int i = TID; i < WU1_U32 / 4; i += 256) d[i] = s[i];
    }
    __syncthreads();

    float C[16][4];
#pragma unroll
    for (int t = 0; t < 16; ++t) {
        float2 b = *(const float2*)(bu1 + t * 8 + q);
        C[t][0] = b.x; C[t][1] = b.y; C[t][2] = b.x; C[t][3] = b.y;
    }

    // two K-phases: A from h (kc 0-7), then from agg (kc 8-15)
#pragma unroll 1
    for (int ph = 0; ph < 2; ++ph) {
        const float* src = ph ? g_agg : h;
        u32 Ah[8][4], Al[8][4];
        {
            const float* ra = src + (size_t)r0 * 128;
            const float* rb = src + (size_t)r1 * 128;
            float2 z = make_float2(0.f, 0.f);
#pragma unroll
            for (int kc = 0; kc < 8; ++kc) {
                float2 a0 = v0 ? *(const float2*)(ra + kc * 16 + q) : z;
                float2 a1 = v1 ? *(const float2*)(rb + kc * 16 + q) : z;
                float2 a2 = v0 ? *(const float2*)(ra + kc * 16 + q + 8) : z;
                float2 a3 = v1 ? *(const float2*)(rb + kc * 16 + q + 8) : z;
                split2(a0.x, a0.y, Ah[kc][0], Al[kc][0]);
                split2(a1.x, a1.y, Ah[kc][1], Al[kc][1]);
                split2(a2.x, a2.y, Ah[kc][2], Al[kc][2]);
                split2(a3.x, a3.y, Ah[kc][3], Al[kc][3]);
            }
        }
#pragma unroll
        for (int p = 0; p < 3; ++p) {
            const u32 (*A)[4] = (p == 1) ? Al : Ah;
            int ver = (p == 2) ? 1 : 0;
#pragma unroll
            for (int kc = 0; kc < 8; ++kc)
#pragma unroll
                for (int t = 0; t < 16; ++t) {
                    uint2 bv = *(const uint2*)(smw + ((((ver * 16 + ph * 8 + kc) * 16 + t) * 32 + l) * 2));
                    mma16816(C[t], A[kc], bv.x, bv.y);
                }
        }
    }

    // relu -> A-fragments for second GEMM (identity layout map)
    u32 Ah[8][4], Al[8][4];
#pragma unroll
    for (int kc = 0; kc < 8; ++kc) {
        split2(fmaxf(C[2 * kc][0], 0.f),     fmaxf(C[2 * kc][1], 0.f),     Ah[kc][0], Al[kc][0]);
        split2(fmaxf(C[2 * kc][2], 0.f),     fmaxf(C[2 * kc][3], 0.f),     Ah[kc][1], Al[kc][1]);
        split2(fmaxf(C[2 * kc + 1][0], 0.f), fmaxf(C[2 * kc + 1][1], 0.f), Ah[kc][2], Al[kc][2]);
        split2(fmaxf(C[2 * kc + 1][2], 0.f), fmaxf(C[2 * kc + 1][3], 0.f), Ah[kc][3], Al[kc][3]);
    }
    __syncthreads();
    {
        const float4* s = (const float4*)g_WU2f;
        float4* d = (float4*)smw;
        for (int i = TID; i < WU2_U32 / 4; i += 256) d[i] = s[i];
    }
    __syncthreads();

#pragma unroll
    for (int hf = 0; hf < 2; ++hf) {
        float C2[8][4];
#pragma unroll
        for (int t = 0; t < 8; ++t) {
            float2 b = *(const float2*)(bu2 + hf * 64 + t * 8 + q);
            C2[t][0] = b.x; C2[t][1] = b.y; C2[t][2] = b.x; C2[t][3] = b.y;
        }
#pragma unroll
        for (int p = 0; p < 3; ++p) {
            const u32 (*A)[4] = (p == 1) ? Al : Ah;
            int ver = (p == 2) ? 1 : 0;
#pragma unroll
            for (int kc = 0; kc < 8; ++kc)
#pragma unroll
                for (int t = 0; t < 8; ++t) {
                    int tt = hf * 8 + t;
                    uint2 bv = *(const uint2*)(smw + ((((ver * 8 + kc) * 16 + tt) * 32 + l) * 2));
                    mma16816(C2[t], A[kc], bv.x, bv.y);
                }
        }
#pragma unroll
        for (int t = 0; t < 8; ++t) {
            int c = hf * 64 + t * 8 + q;
            if (v0) {
                float2 hh = *(const float2*)(h + (size_t)r0 * 128 + c);
                *(float2*)(out + (size_t)r0 * 128 + c) = make_float2(hh.x + C2[t][0], hh.y + C2[t][1]);
            }
            if (v1) {
                float2 hh = *(const float2*)(h + (size_t)r1 * 128 + c);
                *(float2*)(out + (size_t)r1 * 128 + c) = make_float2(hh.x + C2[t][2], hh.y + C2[t][3]);
            }
        }
    }
}

// ---------------------------------------------------------------------------
extern "C" void kernel_launch(void* const* d_in, const int* in_sizes, int n_in,
                              void* d_out, int out_size) {
    const float* h         = (const float*)d_in[0];
    const float* edge_attr = (const float*)d_in[1];
    const float* Wm1       = (const float*)d_in[2];
    const float* bm1       = (const float*)d_in[3];
    const float* Wm2       = (const float*)d_in[4];
    const float* bm2       = (const float*)d_in[5];
    const float* Wu1       = (const float*)d_in[6];
    const float* bu1       = (const float*)d_in[7];
    const float* Wu2       = (const float*)d_in[8];
    const float* bu2       = (const float*)d_in[9];
    const void*  eidx      = (const void*)d_in[10];
    float* out             = (float*)d_out;

    cudaFuncSetAttribute(pq_kernel,     cudaFuncAttributeMaxDynamicSharedMemorySize, PQ2_SMEM);
    cudaFuncSetAttribute(edge_kernel,   cudaFuncAttributeMaxDynamicSharedMemorySize, EDGE_SMEM_B);
    cudaFuncSetAttribute(update_kernel, cudaFuncAttributeMaxDynamicSharedMemorySize, UPD2_SMEM);

    detect_idx_kernel<<<1, 32>>>(eidx);
    convert_idx_kernel<<<(EE + 255) / 256, 256>>>(eidx);
    zero_agg_kernel<<<(NN * 32 + 255) / 256, 256>>>();
    prep_w_kernel<<<(PREP_TOTAL + 255) / 256, 256>>>(Wm1, Wm2, Wu1, Wu2);
    pq_kernel<<<(NN + 127) / 128, 256, PQ2_SMEM>>>(h);
    edge_kernel<<<EE / 128, 256, EDGE_SMEM_B>>>(edge_attr, bm1, bm2);
    update_kernel<<<(NN + 127) / 128, 256, UPD2_SMEM>>>(h, bu1, bu2, out);
}